// round 12
// baseline (speedup 1.0000x reference)
#include <cuda_runtime.h>
#include <cuda_fp16.h>
#include <cstdint>
#include <cstddef>

// ---------------------------------------------------------------------------
// Problem constants
// ---------------------------------------------------------------------------
constexpr int B_ = 256;   // batches
constexpr int N_ = 1024;  // patches
constexpr int M_ = 128;   // words
constexpr int C_ = 512;   // channels (K)

constexpr int NTILE  = 256;          // patch tile per CTA (unit)
constexpr int UNITS_PER_B = N_ / NTILE;  // 4
constexpr int KC     = 32;           // K chunk (fp32 elements)
constexpr int KCH    = C_ / KC;      // 16 chunks per unit
constexpr int SPH    = 40;           // smem row stride in halfs (32 + 8 pad)

// Stage buffer geometry (bytes): A = 128x32 fp16, B = 256x32 fp16 (padded rows)
constexpr int A_SM_BYTES  = 128 * SPH * 2;           // 10240
constexpr int B_SM_BYTES  = 256 * SPH * 2;           // 20480
constexpr int STAGE_BYTES = A_SM_BYTES + B_SM_BYTES; // 30720
constexpr int OFF_Bt      = A_SM_BYTES;

// Float-indexed regions after the two stage buffers
constexpr int MASKF   = (2 * STAGE_BYTES) / 4;   // 15360 (256 floats: this unit's cols)
constexpr int COLWF   = MASKF + 256;             // 4(wm) x 256 floats
constexpr int ROWREDF = COLWF + 1024;            // 128 x 4(wn) floats
constexpr int REDF    = ROWREDF + 512;           // 64 floats
constexpr int SMEM_BYTES = (REDF + 64) * 4;      // 68864

// Global scratch for partials (static __device__: allowed)
__device__ float g_rowmax[B_ * UNITS_PER_B * M_];   // 512 KB
__device__ float g_colsum[B_ * UNITS_PER_B];        // 4 KB

// ---------------------------------------------------------------------------
// Helpers
// ---------------------------------------------------------------------------
__device__ __forceinline__ uint32_t smem_u32(const void* p) {
    uint32_t a;
    asm("{ .reg .u64 t; cvta.to.shared.u64 t, %1; cvt.u32.u64 %0, t; }"
        : "=r"(a) : "l"(p));
    return a;
}

__device__ __forceinline__ void ldm4(uint32_t* r, uint32_t addr) {
    asm volatile("ldmatrix.sync.aligned.m8n8.x4.shared.b16 {%0,%1,%2,%3}, [%4];"
                 : "=r"(r[0]), "=r"(r[1]), "=r"(r[2]), "=r"(r[3]) : "r"(addr));
}

// m16n8k16 row.col fp16 mma, fp32 accumulate (C==D)
__device__ __forceinline__ void mma16(float* c, const uint32_t* a,
                                      uint32_t b0, uint32_t b1) {
    asm volatile(
        "mma.sync.aligned.m16n8k16.row.col.f32.f16.f16.f32 "
        "{%0,%1,%2,%3}, {%4,%5,%6,%7}, {%8,%9}, {%0,%1,%2,%3};"
        : "+f"(c[0]), "+f"(c[1]), "+f"(c[2]), "+f"(c[3])
        : "r"(a[0]), "r"(a[1]), "r"(a[2]), "r"(a[3]), "r"(b0), "r"(b1));
}

// ---------------------------------------------------------------------------
// Main kernel: one CTA per (batch, ntile) unit; 512 threads = 16 warps (4Mx4N).
// Warp tile m32 x n64. Unit tile 128(M) x 256(N), K = 512 in 16 chunks.
// Two-iteration register pipeline (STS never waits on LDG); patch via __ldcs.
// Writes 128 row-maxes + 1 masked col-sum per unit to global scratch.
// ---------------------------------------------------------------------------
__global__ void __launch_bounds__(512, 1)
hrpa_partial(const float* __restrict__ patch,   // (B, N, C)
             const float* __restrict__ word,    // (B, M, C)
             const float* __restrict__ mask)    // (B, N)
{
    extern __shared__ char smc[];
    float* fsm = reinterpret_cast<float*>(smc);
    const uint32_t smb = smem_u32(smc);

    const int tid  = threadIdx.x;
    const int lane = tid & 31;
    const int w    = tid >> 5;     // 0..15
    const int wm   = w & 3;        // M direction (rows wm*32 .. +31)
    const int wn   = w >> 2;       // N direction (cols wn*64 .. +63)
    const int g    = lane >> 2;    // quad group 0..7
    const int tig  = lane & 3;     // thread in group
    const int u    = blockIdx.x;   // unit id
    const int b    = u >> 2;       // batch
    const int nt   = u & 3;        // ntile within batch
    const int n0   = nt * NTILE;

    // ldmatrix per-thread offsets (half units)
    const int mi = lane >> 3, r8 = lane & 7;
    const int aoff = (((mi & 1) << 3) + r8) * SPH + ((mi >> 1) << 3);
    const int boff = (((mi >> 1) << 3) + r8) * SPH + ((mi & 1) << 3);

    const float* wbase = word  + (size_t)b * M_ * C_;
    const float* pbase = patch + (size_t)b * N_ * C_ + (size_t)n0 * C_;

    // loader mapping: slot row = p*64 + (tid>>3), vec4 index = tid&7
    const int lr = tid >> 3;   // 0..63
    const int lv = tid & 7;

    // ---- this unit's mask slice -> smem ----
    if (tid < NTILE) fsm[MASKF + tid] = mask[b * N_ + n0 + tid];

    auto load_regs = [&](int gq, float4* stA, float4* stB) {
        const int k0 = gq * KC;
        #pragma unroll
        for (int p = 0; p < 2; p++) {   // A (word): L2-resident
            const int r = p * 64 + lr;
            stA[p] = *(const float4*)(wbase + (size_t)r * C_ + k0 + lv * 4);
        }
        #pragma unroll
        for (int p = 0; p < 4; p++) {   // B (patch): streaming
            const int r = p * 64 + lr;
            stB[p] = __ldcs((const float4*)(pbase + (size_t)r * C_ + k0 + lv * 4));
        }
    };
    auto sts_stage = [&](int buf, const float4* stA, const float4* stB) {
        char* base = smc + buf * STAGE_BYTES;
        #pragma unroll
        for (int p = 0; p < 2; p++) {
            const int r = p * 64 + lr;
            __half2 h0 = __floats2half2_rn(stA[p].x, stA[p].y);
            __half2 h1 = __floats2half2_rn(stA[p].z, stA[p].w);
            *(uint2*)(base + (r * SPH + lv * 4) * 2) =
                make_uint2(*(uint32_t*)&h0, *(uint32_t*)&h1);
        }
        #pragma unroll
        for (int p = 0; p < 4; p++) {
            const int r = p * 64 + lr;
            __half2 h0 = __floats2half2_rn(stB[p].x, stB[p].y);
            __half2 h1 = __floats2half2_rn(stB[p].z, stB[p].w);
            *(uint2*)(base + OFF_Bt + (r * SPH + lv * 4) * 2) =
                make_uint2(*(uint32_t*)&h0, *(uint32_t*)&h1);
        }
    };

    // ---- prologue: chunk 0 -> buffer 0; chunk 1 held in registers ----
    float4 sA[2], sB[4];
    load_regs(0, sA, sB);
    sts_stage(0, sA, sB);
    load_regs(1, sA, sB);
    __syncthreads();

    float acc[2][8][4];
    #pragma unroll
    for (int mt = 0; mt < 2; mt++)
        #pragma unroll
        for (int j = 0; j < 8; j++)
            #pragma unroll
            for (int q = 0; q < 4; q++) acc[mt][j][q] = 0.f;

    for (int gq = 0; gq < KCH; gq++) {
        // 1. STS chunk gq+1 from registers loaded last iteration (no stall)
        if (gq + 1 < KCH) sts_stage((gq + 1) & 1, sA, sB);
        // 2. LDGs for chunk gq+2 (two iterations of slack)
        if (gq + 2 < KCH) load_regs(gq + 2, sA, sB);

        // 3. MMAs on chunk gq from buffer gq&1
        const uint32_t abase = smb + (uint32_t)((gq & 1) * STAGE_BYTES);
        const uint32_t bbase = abase + OFF_Bt;
        #pragma unroll
        for (int ks = 0; ks < 2; ks++) {
            uint32_t A0[4], A1[4];
            ldm4(A0, abase + (uint32_t)(((wm * 32     ) * SPH) + aoff + ks * 16) * 2);
            ldm4(A1, abase + (uint32_t)(((wm * 32 + 16) * SPH) + aoff + ks * 16) * 2);
            #pragma unroll
            for (int jj = 0; jj < 4; jj++) {
                uint32_t Bf[4];
                ldm4(Bf, bbase + (uint32_t)(((wn * 64 + jj * 16) * SPH) + boff + ks * 16) * 2);
                mma16(acc[0][jj * 2    ], A0, Bf[0], Bf[1]);
                mma16(acc[1][jj * 2    ], A1, Bf[0], Bf[1]);
                mma16(acc[0][jj * 2 + 1], A0, Bf[2], Bf[3]);
                mma16(acc[1][jj * 2 + 1], A1, Bf[2], Bf[3]);
            }
        }
        __syncthreads();
    }

    // ---- epilogue: leaky relu, masked row max, column max ----
    float rmax[4] = {-3.0e38f, -3.0e38f, -3.0e38f, -3.0e38f};
    float colpart[16];
    #pragma unroll
    for (int j = 0; j < 8; j++) {
        #pragma unroll
        for (int cc = 0; cc < 2; cc++) {
            const int col = wn * 64 + j * 8 + 2 * tig + cc;
            const float pen = 1000.f * (1.f - fsm[MASKF + col]);
            float vmax = -3.0e38f;
            #pragma unroll
            for (int mt = 0; mt < 2; mt++) {
                float v0 = acc[mt][j][cc];
                float v1 = acc[mt][j][cc + 2];
                v0 = v0 > 0.f ? v0 : 0.1f * v0;
                v1 = v1 > 0.f ? v1 : 0.1f * v1;
                rmax[mt * 2 + 0] = fmaxf(rmax[mt * 2 + 0], v0 - pen);
                rmax[mt * 2 + 1] = fmaxf(rmax[mt * 2 + 1], v1 - pen);
                vmax = fmaxf(vmax, fmaxf(v0, v1));
            }
            colpart[j * 2 + cc] = vmax;
        }
    }
    #pragma unroll
    for (int off = 4; off <= 16; off <<= 1)
        #pragma unroll
        for (int i = 0; i < 16; i++)
            colpart[i] = fmaxf(colpart[i], __shfl_xor_sync(0xffffffffu, colpart[i], off));
    if (g == 0) {
        #pragma unroll
        for (int j = 0; j < 8; j++)
            #pragma unroll
            for (int cc = 0; cc < 2; cc++)
                fsm[COLWF + wm * NTILE + wn * 64 + j * 8 + 2 * tig + cc] =
                    colpart[j * 2 + cc];
    }

    // row maxes: combine within quad, publish per (row, wn)
    #pragma unroll
    for (int off = 1; off <= 2; off <<= 1)
        #pragma unroll
        for (int i = 0; i < 4; i++)
            rmax[i] = fmaxf(rmax[i], __shfl_xor_sync(0xffffffffu, rmax[i], off));
    if (tig == 0) {
        #pragma unroll
        for (int mt = 0; mt < 2; mt++) {
            fsm[ROWREDF + (wm * 32 + mt * 16 +     g) * 4 + wn] = rmax[mt * 2 + 0];
            fsm[ROWREDF + (wm * 32 + mt * 16 + 8 + g) * 4 + wn] = rmax[mt * 2 + 1];
        }
    }
    __syncthreads();

    // write per-unit row maxes (128 values)
    if (tid < 128) {
        float rm = fmaxf(fmaxf(fsm[ROWREDF + tid * 4 + 0], fsm[ROWREDF + tid * 4 + 1]),
                         fmaxf(fsm[ROWREDF + tid * 4 + 2], fsm[ROWREDF + tid * 4 + 3]));
        g_rowmax[u * M_ + tid] = rm;
    }

    // masked column sum over this unit's 256 columns
    float cs = 0.f;
    if (tid < NTILE) {
        const float cm = fmaxf(
            fmaxf(fsm[COLWF + tid],             fsm[COLWF + NTILE + tid]),
            fmaxf(fsm[COLWF + 2 * NTILE + tid], fsm[COLWF + 3 * NTILE + tid]));
        cs = cm * fsm[MASKF + tid];
    }
    #pragma unroll
    for (int off = 16; off > 0; off >>= 1)
        cs += __shfl_down_sync(0xffffffffu, cs, off);
    if (lane == 0) fsm[REDF + w] = cs;   // warps 0..7 hold partials (w<8)
    __syncthreads();
    if (tid == 0) {
        float s = 0.f;
        #pragma unroll
        for (int i = 0; i < 8; i++) s += fsm[REDF + i];
        g_colsum[u] = s;
    }
}

// ---------------------------------------------------------------------------
// Reduce kernel: one block per batch; combines 4 units.
// ---------------------------------------------------------------------------
__global__ void __launch_bounds__(128)
hrpa_reduce(const float* __restrict__ mask,   // (B, N)
            float* __restrict__ out)          // (B, 1)
{
    __shared__ float red[8];
    const int b = blockIdx.x, tid = threadIdx.x, lane = tid & 31, w = tid >> 5;

    // per-row max over the 4 units
    float rm = g_rowmax[(b * 4 + 0) * M_ + tid];
    rm = fmaxf(rm, g_rowmax[(b * 4 + 1) * M_ + tid]);
    rm = fmaxf(rm, g_rowmax[(b * 4 + 2) * M_ + tid]);
    rm = fmaxf(rm, g_rowmax[(b * 4 + 3) * M_ + tid]);

    // mask sum
    float ms = 0.f;
    #pragma unroll
    for (int k = 0; k < 8; k++) ms += mask[b * N_ + k * 128 + tid];

    float rs = rm;
    #pragma unroll
    for (int off = 16; off > 0; off >>= 1) {
        rs += __shfl_down_sync(0xffffffffu, rs, off);
        ms += __shfl_down_sync(0xffffffffu, ms, off);
    }
    if (lane == 0) { red[w] = rs; red[4 + w] = ms; }
    __syncthreads();
    if (tid == 0) {
        float rsum = red[0] + red[1] + red[2] + red[3];
        float msum = red[4] + red[5] + red[6] + red[7];
        float csum = g_colsum[b * 4 + 0] + g_colsum[b * 4 + 1] +
                     g_colsum[b * 4 + 2] + g_colsum[b * 4 + 3];
        out[b] = rsum * (1.f / 128.f) + csum / (msum + 1e-8f);
    }
}

// ---------------------------------------------------------------------------
// Host launch
// ---------------------------------------------------------------------------
extern "C" void kernel_launch(void* const* d_in, const int* in_sizes, int n_in,
                              void* d_out, int out_size)
{
    (void)in_sizes; (void)n_in; (void)out_size;
    const float* patch = (const float*)d_in[0];  // (B, N, C)
    const float* word  = (const float*)d_in[1];  // (B, M, C)
    const float* mask  = (const float*)d_in[2];  // (B, N)
    float* out = (float*)d_out;                  // (B, 1)

    cudaFuncSetAttribute(hrpa_partial,
                         cudaFuncAttributeMaxDynamicSharedMemorySize, SMEM_BYTES);
    hrpa_partial<<<B_ * UNITS_PER_B, 512, SMEM_BYTES>>>(patch, word, mask);
    hrpa_reduce<<<B_, 128>>>(mask, out);
}